// round 17
// baseline (speedup 1.0000x reference)
#include <cuda_runtime.h>
#include <cuda_fp16.h>

typedef unsigned long long u64;
typedef unsigned int u32;
typedef unsigned short u16;

// ---------------- smem layout (bytes) ----------------
#define QHo   0        // Q/t fp16: 128 rows x 264 halves (stride 528B) = 67584
#define PBo   67584    // 4 rotating buffers x 18432 = 73728
#define CSTo  141312   // 1024 floats: bq(256) bg(256) bo(256) bc1(128) wc2(128)
#define SMEM_BYTES 145408

// ---------------- prepped global images (fp16) ----------------
// W images packed [kc][n][64]; elem bases: Wg=0, Wc1=65536, Wq=98304, Wo=163840
__device__ uint4 g_Wh_img[28672];
__device__ uint4 g_knh[2][4][512];   // normalized keys [s][d] 64x64
__device__ uint4 g_vth[2][4][512];   // values transposed [d][s] 64x64

// chunk stream: gate(0-7) conf(8-11) Wq(12-19) attn(20-27) Wo(28-35), +3 sentinels
// attn code = 0x80000000 | (tier<<3) | h ; sentinel = 0xFFFFFFFF
__constant__ u32 g_stream[39] = {
    0u, 16384u, 32768u, 49152u, 8192u, 24576u, 40960u, 57344u,          // gate nh0 kc0-3, nh1 kc0-3
    65536u, 73728u, 81920u, 90112u,                                     // conf kc0-3
    98304u, 114688u, 131072u, 147456u, 106496u, 122880u, 139264u, 155648u, // Wq nh0, nh1
    0x80000000u, 0x80000008u, 0x80000001u, 0x80000009u,                 // (h0,F)(h0,D)(h1,F)(h1,D)
    0x80000002u, 0x8000000Au, 0x80000003u, 0x8000000Bu,                 // (h2,F)(h2,D)(h3,F)(h3,D)
    163840u, 180224u, 196608u, 212992u, 172032u, 188416u, 204800u, 221184u, // Wo nh0, nh1
    0xFFFFFFFFu, 0xFFFFFFFFu, 0xFFFFFFFFu
};

// ---------------- helpers ----------------
__device__ __forceinline__ u32 pk2h(float x, float y) {   // lo=x, hi=y
    u32 r; asm("cvt.rn.f16x2.f32 %0, %1, %2;" : "=r"(r) : "f"(y), "f"(x)); return r;
}
__device__ __forceinline__ u32 smaddr(const void* p) {
    u32 a;
    asm("{ .reg .u64 t; cvta.to.shared.u64 t, %1; cvt.u32.u64 %0, t; }" : "=r"(a) : "l"(p));
    return a;
}
__device__ __forceinline__ void ldsm4(u32 a, u32& r0, u32& r1, u32& r2, u32& r3) {
    asm volatile("ldmatrix.sync.aligned.m8n8.x4.shared.b16 {%0,%1,%2,%3}, [%4];"
                 : "=r"(r0), "=r"(r1), "=r"(r2), "=r"(r3) : "r"(a));
}
__device__ __forceinline__ void mmab(float* c, u32 a0, u32 a1, u32 a2, u32 a3, u32 b0, u32 b1) {
    asm volatile(
        "mma.sync.aligned.m16n8k16.row.col.f32.f16.f16.f32 "
        "{%0,%1,%2,%3}, {%4,%5,%6,%7}, {%8,%9}, {%0,%1,%2,%3};"
        : "+f"(c[0]), "+f"(c[1]), "+f"(c[2]), "+f"(c[3])
        : "r"(a0), "r"(a1), "r"(a2), "r"(a3), "r"(b0), "r"(b1));
}
__device__ __forceinline__ float tanha(float x) {
    float y; asm("tanh.approx.f32 %0, %1;" : "=f"(y) : "f"(x)); return y;
}
#define CPA16(d, s) asm volatile("cp.async.cg.shared.global [%0], [%1], 16;" :: "r"(d), "l"(s) : "memory")
#define COMMIT()    asm volatile("cp.async.commit_group;" ::: "memory")
#define WAITG0()    asm volatile("cp.async.wait_group 0;" ::: "memory")
#define WAITG1()    asm volatile("cp.async.wait_group 1;" ::: "memory")
#define WAITG2()    asm volatile("cp.async.wait_group 2;" ::: "memory")

// fill one buffer with a 128x64 W chunk (hi only); one commit group
__device__ __forceinline__ void prefW(u32 buf, u32 baseE, int tid) {
    const uint4* sH = g_Wh_img + (baseE >> 3);
    #pragma unroll
    for (int i = tid; i < 1024; i += 256) {
        CPA16(buf + (u32)(i >> 3) * 144 + (u32)(i & 7) * 16, (const void*)(sH + i));
    }
    COMMIT();
}
// fill one buffer with (kn @0, vT @9216) for one (tier,h); one commit group
__device__ __forceinline__ void prefPair(u32 buf, int tier, int h, int tid) {
    const uint4* s0 = g_knh[tier][h];
    const uint4* s1 = g_vth[tier][h];
    #pragma unroll
    for (int i = tid; i < 512; i += 256) {
        u32 d = (u32)(i >> 3) * 144 + (u32)(i & 7) * 16;
        CPA16(buf + d,        (const void*)(s0 + i));
        CPA16(buf + 9216 + d, (const void*)(s1 + i));
    }
    COMMIT();
}
__device__ __forceinline__ void pref_any(u32 code, u32 buf, int tid) {
    if (code == 0xFFFFFFFFu) return;
    if (code & 0x80000000u) prefPair(buf, (int)((code >> 3) & 1u), (int)(code & 7u), tid);
    else prefW(buf, code, tid);
}
// per-chunk head: wait for chunk g's data, barrier, prefetch chunk g+3
__device__ __forceinline__ void step(int g, u32 Pbase, int tid) {
    if (g == 34) { WAITG1(); } else if (g == 35) { WAITG0(); } else { WAITG2(); }
    __syncthreads();
    pref_any(g_stream[g + 3], Pbase + (u32)((g + 3) & 3) * 18432u, tid);
}

// one K=64 stage: C[2*NP][4] += A(16 rows,64 cols) @ B(NP*16 rows,64 cols)^T (1-term fp16)
template<int NP>
__device__ __forceinline__ void gemm_stage(float (*C)[4], u32 aH, u32 bH) {
    #pragma unroll
    for (int kt = 0; kt < 4; kt++) {
        u32 a0, a1, a2, a3;
        ldsm4(aH + kt * 32, a0, a1, a2, a3);
        #pragma unroll
        for (int np = 0; np < NP; np++) {
            u32 b0, b1, b2, b3;
            ldsm4(bH + np * 2304 + kt * 32, b0, b1, b2, b3);
            mmab(C[2 * np], a0, a1, a2, a3, b0, b1);
            mmab(C[2 * np + 1], a0, a1, a2, a3, b2, b3);
        }
    }
}

// stage fp32 [128x256] -> QBUF fp16 (stride 528)
__device__ __forceinline__ void stageQ(char* sma, const float* __restrict__ src, int tid) {
    #pragma unroll 4
    for (int i = tid; i < 8192; i += 256) {
        int r = i >> 6, c4 = i & 63;
        float4 v = *(const float4*)(src + (size_t)r * 256 + c4 * 4);
        u32 h0 = pk2h(v.x, v.y), h1 = pk2h(v.z, v.w);
        *(u64*)(sma + QHo + r * 528 + c4 * 8) = (u64)h0 | ((u64)h1 << 32);
    }
}

// ---------------- prep kernels ----------------
__global__ void prep_W(const float* __restrict__ Wq, const float* __restrict__ Wg,
                       const float* __restrict__ Wc1, const float* __restrict__ Wo) {
    int t = blockIdx.x * blockDim.x + threadIdx.x;   // 0..57343
    const float* src; int N; u32 base; int tt;
    if (t < 16384)      { src = Wg;  N = 256; base = 0u;      tt = t; }
    else if (t < 24576) { src = Wc1; N = 128; base = 65536u;  tt = t - 16384; }
    else if (t < 40960) { src = Wq;  N = 256; base = 98304u;  tt = t - 24576; }
    else                { src = Wo;  N = 256; base = 163840u; tt = t - 40960; }
    int n = tt >> 6, c4 = tt & 63;
    int kc = c4 >> 4, kk = (c4 & 15) * 4;
    float4 v = *(const float4*)(src + (size_t)n * 256 + c4 * 4);
    u32 h0 = pk2h(v.x, v.y), h1 = pk2h(v.z, v.w);
    u32 e = base + (u32)(kc * N + n) * 64 + (u32)kk;
    ((u64*)g_Wh_img)[e >> 2] = (u64)h0 | ((u64)h1 << 32);
}

__global__ void prep_kv(const float* __restrict__ fk, const float* __restrict__ fv,
                        const float* __restrict__ dk, const float* __restrict__ dv) {
    int t = blockIdx.x * blockDim.x + threadIdx.x;
    if (t >= 512) return;
    int tier = t >> 8, rem = t & 255, h = rem >> 6, s = rem & 63;
    const float* K = (tier ? dk : fk) + (h * 64 + s) * 64;
    const float* V = (tier ? dv : fv) + (h * 64 + s) * 64;
    float ss = 0.f;
    for (int d = 0; d < 64; d++) { float v = K[d]; ss += v * v; }
    float r = 1.0f / (sqrtf(ss) + 1e-8f);
    u16* knh = (u16*)g_knh[tier][h];
    u16* vth = (u16*)g_vth[tier][h];
    for (int d = 0; d < 64; d++) {
        knh[s * 64 + d] = __half_as_ushort(__float2half_rn(K[d] * r));
        vth[d * 64 + s] = __half_as_ushort(__float2half_rn(V[d]));
    }
}

// ---------------- main kernel ----------------
__global__ void __launch_bounds__(256, 1) miras_mma(
    const float* __restrict__ query, const float* __restrict__ context,
    const float* __restrict__ bq, const float* __restrict__ bg,
    const float* __restrict__ bc1, const float* __restrict__ Wc2,
    const float* __restrict__ bc2, const float* __restrict__ bo,
    const float* __restrict__ mixl, float* __restrict__ outp)
{
    extern __shared__ char sma[];
    const u32 sb = smaddr(sma);
    const int tid = threadIdx.x, lane = tid & 31, warp = tid >> 5;
    const int mb = warp * 16;
    const size_t m0 = (size_t)blockIdx.x * 128;
    float* cst = (float*)(sma + CSTo);
    const u32 Pb = sb + PBo;

    { int i = tid; cst[i] = bq[i]; cst[256 + i] = bg[i]; cst[512 + i] = bo[i]; }
    if (tid < 128) { cst[768 + tid] = bc1[tid]; cst[896 + tid] = Wc2[tid]; }
    const float mixl_v = __ldg(mixl), bc2v = __ldg(bc2);

    // lane-resolved ldmatrix offsets
    const u32 arow = (u32)(((lane >> 3) & 1) * 8 + (lane & 7));
    const u32 aOffQ = (u32)(mb + arow) * 528 + (u32)(lane >> 4) * 16;
    const u32 bOff  = (u32)(((lane >> 4) & 1) * 8 + (lane & 7)) * 144 + (u32)((lane >> 3) & 1) * 16;
    const u32 qH0 = sb + QHo + aOffQ;

    // prolog: chunks 0,1,2 in flight; stage context
    prefW(Pb + 0u * 18432u, g_stream[0], tid);
    prefW(Pb + 1u * 18432u, g_stream[1], tid);
    prefW(Pb + 2u * 18432u, g_stream[2], tid);
    stageQ(sma, context + m0 * 256, tid);

    float C16[16][4];
    float ga0 = 0.f, ga1 = 0.f, ca0 = 0.f, ca1 = 0.f;

    // ---------- chunks 0-11: gate (8) + conf (4), A = context ----------
    #pragma unroll
    for (int t = 0; t < 16; t++) { C16[t][0] = C16[t][1] = C16[t][2] = C16[t][3] = 0.f; }
    #pragma unroll 1
    for (int g = 0; g < 12; g++) {
        step(g, Pb, tid);
        u32 buf = Pb + (u32)(g & 3) * 18432u;
        gemm_stage<8>(C16, qH0 + (u32)(g & 3) * 128, buf + bOff);
        if (g == 3 || g == 7) {
            int nh = (g == 7);
            #pragma unroll
            for (int t = 0; t < 16; t++) {
                int col = nh * 128 + t * 8 + (lane & 3) * 2;
                ga0 += tanha(C16[t][0] + cst[256 + col]) + tanha(C16[t][1] + cst[256 + col + 1]);
                ga1 += tanha(C16[t][2] + cst[256 + col]) + tanha(C16[t][3] + cst[256 + col + 1]);
                C16[t][0] = C16[t][1] = C16[t][2] = C16[t][3] = 0.f;
            }
        } else if (g == 11) {
            #pragma unroll
            for (int t = 0; t < 16; t++) {
                int col = t * 8 + (lane & 3) * 2;
                ca0 += tanha(C16[t][0] + cst[768 + col]) * cst[896 + col]
                     + tanha(C16[t][1] + cst[768 + col + 1]) * cst[896 + col + 1];
                ca1 += tanha(C16[t][2] + cst[768 + col]) * cst[896 + col]
                     + tanha(C16[t][3] + cst[768 + col + 1]) * cst[896 + col + 1];
            }
        }
    }

    // drain QBUF readers, restage with query (chunks 12-14 already in flight)
    __syncthreads();
    stageQ(sma, query + m0 * 256, tid);

    ga0 += __shfl_xor_sync(0xffffffffu, ga0, 1); ga0 += __shfl_xor_sync(0xffffffffu, ga0, 2);
    ga1 += __shfl_xor_sync(0xffffffffu, ga1, 1); ga1 += __shfl_xor_sync(0xffffffffu, ga1, 2);
    ca0 += __shfl_xor_sync(0xffffffffu, ca0, 1); ca0 += __shfl_xor_sync(0xffffffffu, ca0, 2);
    ca1 += __shfl_xor_sync(0xffffffffu, ca1, 1); ca1 += __shfl_xor_sync(0xffffffffu, ca1, 2);
    float mix0 = 1.f / (1.f + __expf(-(mixl_v + ga0 * (1.f / 256.f))));
    float mix1 = 1.f / (1.f + __expf(-(mixl_v + ga1 * (1.f / 256.f))));
    float cf0 = 1.f / (1.f + __expf(-(ca0 + bc2v)));
    float cf1 = 1.f / (1.f + __expf(-(ca1 + bc2v)));
    float aF0 = mix0 * cf0, aD0 = (1.f - mix0) * cf0;
    float aF1 = mix1 * cf1, aD1 = (1.f - mix1) * cf1;

    // ---------- chunks 12-19: Q = query @ Wq^T + bq (both halves in C32; in-place safe) ----------
    {
        float C[32][4];
        #pragma unroll
        for (int t = 0; t < 32; t++) { C[t][0] = C[t][1] = C[t][2] = C[t][3] = 0.f; }
        #pragma unroll 1
        for (int g = 12; g < 20; g++) {
            step(g, Pb, tid);
            u32 buf = Pb + (u32)(g & 3) * 18432u;
            gemm_stage<8>(C + ((g >= 16) ? 16 : 0), qH0 + (u32)(g & 3) * 128, buf + bOff);
        }
        // epilogue: +bq, per-head norms, write Q fp16 over QBUF (own rows only)
        float ssqA[4] = {0.f, 0.f, 0.f, 0.f}, ssqB[4] = {0.f, 0.f, 0.f, 0.f};
        #pragma unroll
        for (int t = 0; t < 32; t++) {
            int col = (t >> 4) * 128 + (t & 15) * 8 + (lane & 3) * 2;
            float v0 = C[t][0] + cst[col], v1 = C[t][1] + cst[col + 1];
            float v2 = C[t][2] + cst[col], v3 = C[t][3] + cst[col + 1];
            int hh = col >> 6;
            ssqA[hh] += v0 * v0 + v1 * v1;
            ssqB[hh] += v2 * v2 + v3 * v3;
            char* p = sma + QHo + (mb + (lane >> 2)) * 528 + col * 2;
            *(u32*)p = pk2h(v0, v1);
            *(u32*)(p + 8 * 528) = pk2h(v2, v3);
        }
        float rqA[4], rqB[4];
        #pragma unroll
        for (int hh = 0; hh < 4; hh++) {
            float s = ssqA[hh];
            s += __shfl_xor_sync(0xffffffffu, s, 1); s += __shfl_xor_sync(0xffffffffu, s, 2);
            rqA[hh] = 1.f / (sqrtf(s) + 1e-8f);
            s = ssqB[hh];
            s += __shfl_xor_sync(0xffffffffu, s, 1); s += __shfl_xor_sync(0xffffffffu, s, 2);
            rqB[hh] = 1.f / (sqrtf(s) + 1e-8f);
        }

        // ---------- chunks 20-27: dual-tier attention (buffer = kn@0, vT@9216) ----------
        float T[8][4];
        #pragma unroll 1
        for (int g = 20; g < 28; g++) {
            const int h = (g - 20) >> 1, tier = (g - 20) & 1;
            step(g, Pb, tid);
            const u32 buf = Pb + (u32)(g & 3) * 18432u;
            if (tier == 0) {
                #pragma unroll
                for (int t = 0; t < 8; t++) { T[t][0] = T[t][1] = T[t][2] = T[t][3] = 0.f; }
            }
            float rq0 = rqA[h], rq1 = rqB[h];
            float sc0 = tier ? aD0 : aF0, sc1 = tier ? aD1 : aF1;

            float S[8][4];
            #pragma unroll
            for (int t = 0; t < 8; t++) { S[t][0] = S[t][1] = S[t][2] = S[t][3] = 0.f; }
            gemm_stage<4>(S, qH0 + (u32)h * 128, buf + bOff);

            float mx0 = -1e30f, mx1 = -1e30f;
            #pragma unroll
            for (int t = 0; t < 8; t++) {
                S[t][0] *= rq0; S[t][1] *= rq0; S[t][2] *= rq1; S[t][3] *= rq1;
                mx0 = fmaxf(mx0, fmaxf(S[t][0], S[t][1]));
                mx1 = fmaxf(mx1, fmaxf(S[t][2], S[t][3]));
            }
            mx0 = fmaxf(mx0, __shfl_xor_sync(0xffffffffu, mx0, 1));
            mx0 = fmaxf(mx0, __shfl_xor_sync(0xffffffffu, mx0, 2));
            mx1 = fmaxf(mx1, __shfl_xor_sync(0xffffffffu, mx1, 1));
            mx1 = fmaxf(mx1, __shfl_xor_sync(0xffffffffu, mx1, 2));
            float su0 = 0.f, su1 = 0.f;
            #pragma unroll
            for (int t = 0; t < 8; t++) {
                S[t][0] = __expf(S[t][0] - mx0); S[t][1] = __expf(S[t][1] - mx0);
                S[t][2] = __expf(S[t][2] - mx1); S[t][3] = __expf(S[t][3] - mx1);
                su0 += S[t][0] + S[t][1];
                su1 += S[t][2] + S[t][3];
            }
            su0 += __shfl_xor_sync(0xffffffffu, su0, 1); su0 += __shfl_xor_sync(0xffffffffu, su0, 2);
            su1 += __shfl_xor_sync(0xffffffffu, su1, 1); su1 += __shfl_xor_sync(0xffffffffu, su1, 2);
            float iv0 = sc0 / su0, iv1 = sc1 / su1;

            u32 pH[8][2];
            #pragma unroll
            for (int t = 0; t < 8; t++) {
                pH[t][0] = pk2h(S[t][0] * iv0, S[t][1] * iv0);
                pH[t][1] = pk2h(S[t][2] * iv1, S[t][3] * iv1);
            }
            #pragma unroll
            for (int kt = 0; kt < 4; kt++) {
                u32 a0 = pH[2*kt][0], a1 = pH[2*kt][1], a2 = pH[2*kt+1][0], a3 = pH[2*kt+1][1];
                #pragma unroll
                for (int np = 0; np < 4; np++) {
                    u32 b0, b1, b2, b3;
                    ldsm4(buf + 9216 + bOff + np * 2304 + kt * 32, b0, b1, b2, b3);
                    mmab(T[2*np],   a0, a1, a2, a3, b0, b1);
                    mmab(T[2*np+1], a0, a1, a2, a3, b2, b3);
                }
            }

            if (tier == 1) {
                #pragma unroll
                for (int t = 0; t < 8; t++) {
                    int col = h * 64 + t * 8 + (lane & 3) * 2;
                    char* p = sma + QHo + (mb + (lane >> 2)) * 528 + col * 2;
                    *(u32*)p = pk2h(T[t][0], T[t][1]);
                    *(u32*)(p + 8 * 528) = pk2h(T[t][2], T[t][3]);
                }
                __syncwarp();
            }
        }
    }

    // ---------- chunks 28-35: out = t @ Wo^T + bo (per-half C16 epilogues) ----------
    #pragma unroll
    for (int t = 0; t < 16; t++) { C16[t][0] = C16[t][1] = C16[t][2] = C16[t][3] = 0.f; }
    #pragma unroll 1
    for (int g = 28; g < 36; g++) {
        step(g, Pb, tid);
        u32 buf = Pb + (u32)(g & 3) * 18432u;
        gemm_stage<8>(C16, qH0 + (u32)(g & 3) * 128, buf + bOff);
        if (g == 31 || g == 35) {
            int half = (g == 35);
            #pragma unroll
            for (int t = 0; t < 16; t++) {
                int col = half * 128 + t * 8 + (lane & 3) * 2;
                size_t r0 = m0 + mb + (lane >> 2);
                float2 o0 = make_float2(C16[t][0] + cst[512 + col], C16[t][1] + cst[512 + col + 1]);
                *(float2*)(outp + r0 * 256 + col) = o0;
                float2 o1 = make_float2(C16[t][2] + cst[512 + col], C16[t][3] + cst[512 + col + 1]);
                *(float2*)(outp + (r0 + 8) * 256 + col) = o1;
                C16[t][0] = C16[t][1] = C16[t][2] = C16[t][3] = 0.f;
            }
        }
    }
}

extern "C" void kernel_launch(void* const* d_in, const int* in_sizes, int n_in,
                              void* d_out, int out_size) {
    (void)in_sizes; (void)n_in; (void)out_size;
    const float* query   = (const float*)d_in[0];
    const float* context = (const float*)d_in[1];
    const float* fk  = (const float*)d_in[2];
    const float* fv  = (const float*)d_in[3];
    const float* dk  = (const float*)d_in[4];
    const float* dv  = (const float*)d_in[5];
    const float* Wq  = (const float*)d_in[6];
    const float* bq  = (const float*)d_in[7];
    const float* Wg  = (const float*)d_in[8];
    const float* bg  = (const float*)d_in[9];
    const float* Wc1 = (const float*)d_in[10];
    const float* bc1 = (const float*)d_in[11];
    const float* Wc2 = (const float*)d_in[12];
    const float* bc2 = (const float*)d_in[13];
    const float* Wo  = (const float*)d_in[14];
    const float* bo  = (const float*)d_in[15];
    const float* mixl = (const float*)d_in[18];
    float* out = (float*)d_out;

    cudaFuncSetAttribute(miras_mma, cudaFuncAttributeMaxDynamicSharedMemorySize, SMEM_BYTES);

    prep_W<<<224, 256>>>(Wq, Wg, Wc1, Wo);
    prep_kv<<<2, 256>>>(fk, fv, dk, dv);
    miras_mma<<<512, 256, SMEM_BYTES>>>(query, context, bq, bg, bc1, Wc2, bc2, bo, mixl, out);
}